// round 16
// baseline (speedup 1.0000x reference)
#include <cuda_runtime.h>
#include <cuda_fp16.h>
#include <math.h>
#include <stdint.h>

// Problem constants
#define NN 8000
#define EE 200000
#define BB 16
#define DD 256
#define LLAYERS 4

#define KPAD_NODE 272   // 262 rounded up to 16
#define KPAD_EDGE 608   // 600 rounded up to 16

// ---------------- scratch (static device globals; no allocation) ----------------
__device__ float g_lfeat[BB * 6];
__device__ float g_Xnode[NN * KPAD_NODE];
__device__ float g_hn[NN * DD];
__device__ __half g_XedgeH[(size_t)EE * KPAD_EDGE];  // fp16 storage
__device__ __half g_heH[(size_t)EE * DD];            // fp16 storage
__device__ float g_QKVn[(size_t)NN * 768];
__device__ __half g_QKeH[(size_t)EE * 2048];         // 4 layers x [Q|K], fp16, stride 2048
__device__ float g_sc[(size_t)EE * 4];
__device__ float g_invden[NN * 4];
__device__ float g_attn[NN * DD];
__device__ __half g_aggGH[(size_t)NN * 1024];        // fp16 storage
__device__ float g_ffn1[NN * 1024];
__device__ float g_tmp[NN * DD];
__device__ float g_Wn[LLAYERS * 256 * 768];
__device__ float g_We[256 * 2048];
__device__ float g_WvBD[LLAYERS * 1024 * 256];
__device__ float g_bqkv[LLAYERS * 768];
__device__ int   g_deg[NN];
__device__ int   g_rowptr[NN + 1];
__device__ int   g_pos[NN];
__device__ int   g_order[EE];

// ---------------- helpers ----------------
__device__ __forceinline__ float gelu_f(float x) {
    return 0.5f * x * (1.0f + erff(x * 0.70710678118654752f));
}
__device__ __forceinline__ float wredsum(float v) {
    for (int o = 16; o > 0; o >>= 1) v += __shfl_xor_sync(0xffffffffu, v, o);
    return v;
}
__device__ __forceinline__ float wredmax(float v) {
    for (int o = 16; o > 0; o >>= 1) v = fmaxf(v, __shfl_xor_sync(0xffffffffu, v, o));
    return v;
}
__device__ __forceinline__ uint32_t f2tf(float x) {
    uint32_t r;
    asm("cvt.rna.tf32.f32 %0, %1;" : "=r"(r) : "f"(x));
    return r;
}

// ---------------- tf32 tensor-core GEMM: C = act(A @ B + bias [+ res]) ----------------
// Tiles: BM=128 BN=128 BK=16. 256 threads = 8 warps (4 along M x 2 along N).
// Warp tile 32x64 via mma.sync.m16n8k8 (proven config).
// AH: A elements are __half (else float). OH: C elements are __half (else float).
#define SSTR 136   // 128 + 8 padding -> conflict-free fragment reads

template <int ACT, int AH, int OH>
__global__ void __launch_bounds__(256) tgemm_k(
    int M, int K,
    const void* __restrict__ Ap, int lda,
    const float* __restrict__ B, int ldb,
    const float* __restrict__ bias,
    const float* __restrict__ res,
    void* __restrict__ Cp, int ldc)
{
    __shared__ uint32_t As[2][16][SSTR];
    __shared__ uint32_t Bs[2][16][SSTR];
    const float*  Af = (const float*)Ap;
    const __half* Ah = (const __half*)Ap;
    const int tid = threadIdx.x;
    const int bn = blockIdx.x * 128;
    const int bm = blockIdx.y * 128;
    const int warp = tid >> 5, lane = tid & 31;
    const int wm = (warp & 3) * 32;
    const int wn = (warp >> 2) * 64;
    const int grp = lane >> 2, t4 = lane & 3;

    float acc[2][8][4];
#pragma unroll
    for (int i = 0; i < 2; i++)
#pragma unroll
        for (int j = 0; j < 8; j++)
#pragma unroll
            for (int q = 0; q < 4; q++) acc[i][j][q] = 0.f;

    const int kiters = (K + 15) >> 4;

    float4 ar[2], br[2];

    auto loadg = [&](int k0) {
#pragma unroll
        for (int l = 0; l < 2; l++) {
            const int idx = tid + l * 256;
            const int r = idx >> 2, cg = idx & 3;           // A: 128 rows x 4 k-groups
            const int gm = bm + r;
            if (gm < M) {
                if (AH) {
                    const uint2 u = *(const uint2*)(Ah + (size_t)gm * lda + k0 + cg * 4);
                    const float2 f0 = __half22float2(*(const __half2*)&u.x);
                    const float2 f1 = __half22float2(*(const __half2*)&u.y);
                    ar[l] = make_float4(f0.x, f0.y, f1.x, f1.y);
                } else {
                    ar[l] = *(const float4*)(Af + (size_t)gm * lda + k0 + cg * 4);
                }
            } else ar[l] = make_float4(0.f, 0.f, 0.f, 0.f);
            const int row = idx >> 5, c4 = idx & 31;        // B: 16 rows x 32 col-groups
            const int gk = k0 + row;
            if (gk < K) br[l] = *(const float4*)(B + (size_t)gk * ldb + bn + c4 * 4);
            else        br[l] = make_float4(0.f, 0.f, 0.f, 0.f);
        }
    };
    auto store_s = [&](int buf) {
#pragma unroll
        for (int l = 0; l < 2; l++) {
            const int idx = tid + l * 256;
            const int r = idx >> 2, cg = idx & 3;
            As[buf][cg * 4 + 0][r] = f2tf(ar[l].x);
            As[buf][cg * 4 + 1][r] = f2tf(ar[l].y);
            As[buf][cg * 4 + 2][r] = f2tf(ar[l].z);
            As[buf][cg * 4 + 3][r] = f2tf(ar[l].w);
            const int row = idx >> 5, c4 = idx & 31;
            uint32_t* p = &Bs[buf][row][c4 * 4];
            p[0] = f2tf(br[l].x); p[1] = f2tf(br[l].y);
            p[2] = f2tf(br[l].z); p[3] = f2tf(br[l].w);
        }
    };
    auto compute = [&](int buf) {
#pragma unroll
        for (int ks = 0; ks < 2; ks++) {
            uint32_t af[2][4], bf[8][2];
#pragma unroll
            for (int mb = 0; mb < 2; mb++) {
                const int m0 = wm + mb * 16;
                af[mb][0] = As[buf][ks * 8 + t4][m0 + grp];
                af[mb][1] = As[buf][ks * 8 + t4][m0 + grp + 8];
                af[mb][2] = As[buf][ks * 8 + t4 + 4][m0 + grp];
                af[mb][3] = As[buf][ks * 8 + t4 + 4][m0 + grp + 8];
            }
#pragma unroll
            for (int nb = 0; nb < 8; nb++) {
                const int n0 = wn + nb * 8;
                bf[nb][0] = Bs[buf][ks * 8 + t4][n0 + grp];
                bf[nb][1] = Bs[buf][ks * 8 + t4 + 4][n0 + grp];
            }
#pragma unroll
            for (int mb = 0; mb < 2; mb++)
#pragma unroll
                for (int nb = 0; nb < 8; nb++) {
                    float* c = acc[mb][nb];
                    asm volatile(
                        "mma.sync.aligned.m16n8k8.row.col.f32.tf32.tf32.f32 "
                        "{%0,%1,%2,%3}, {%4,%5,%6,%7}, {%8,%9}, {%0,%1,%2,%3};\n"
                        : "+f"(c[0]), "+f"(c[1]), "+f"(c[2]), "+f"(c[3])
                        : "r"(af[mb][0]), "r"(af[mb][1]), "r"(af[mb][2]), "r"(af[mb][3]),
                          "r"(bf[nb][0]), "r"(bf[nb][1]));
                }
        }
    };

    loadg(0);
    store_s(0);
    __syncthreads();
    int buf = 0;
    for (int ki = 1; ki < kiters; ki++) {
        loadg(ki * 16);
        compute(buf);
        store_s(buf ^ 1);
        __syncthreads();
        buf ^= 1;
    }
    compute(buf);

    // ---- epilogue ----
#pragma unroll
    for (int mb = 0; mb < 2; mb++) {
        const int r0 = bm + wm + mb * 16 + grp;
#pragma unroll
        for (int nb = 0; nb < 8; nb++) {
            const int gn = bn + wn + nb * 8 + t4 * 2;
            float b0v = 0.f, b1v = 0.f;
            if (bias) { b0v = bias[gn]; b1v = bias[gn + 1]; }
            float v0 = acc[mb][nb][0] + b0v, v1 = acc[mb][nb][1] + b1v;
            float v2 = acc[mb][nb][2] + b0v, v3 = acc[mb][nb][3] + b1v;
            if (res) {
                if (r0 < M) {
                    v0 += res[(size_t)r0 * ldc + gn];
                    v1 += res[(size_t)r0 * ldc + gn + 1];
                }
                if (r0 + 8 < M) {
                    v2 += res[(size_t)(r0 + 8) * ldc + gn];
                    v3 += res[(size_t)(r0 + 8) * ldc + gn + 1];
                }
            }
            if (ACT == 1) { v0 = gelu_f(v0); v1 = gelu_f(v1); v2 = gelu_f(v2); v3 = gelu_f(v3); }
            if (OH) {
                __half* C = (__half*)Cp;
                if (r0 < M)     *(__half2*)(C + (size_t)r0 * ldc + gn)       = __floats2half2_rn(v0, v1);
                if (r0 + 8 < M) *(__half2*)(C + (size_t)(r0 + 8) * ldc + gn) = __floats2half2_rn(v2, v3);
            } else {
                float* C = (float*)Cp;
                if (r0 < M)     *(float2*)(C + (size_t)r0 * ldc + gn)       = make_float2(v0, v1);
                if (r0 + 8 < M) *(float2*)(C + (size_t)(r0 + 8) * ldc + gn) = make_float2(v2, v3);
            }
        }
    }
}

// ---------------- weight packing ----------------
// Node: g_Wn[l][k][n768] = [Wq_top | Wkv_top] (Q,K,V).
__global__ void k_pack(const float* __restrict__ Wq, const float* __restrict__ Wkv) {
    const int idx = blockIdx.x * 256 + threadIdx.x;
    if (idx >= LLAYERS * 256 * 768) return;
    const int l = idx / (256 * 768);
    const int rem = idx - l * 256 * 768;
    const int k = rem / 768, n = rem - k * 768;
    float vn;
    if (n < 256) vn = Wq[((size_t)l * 512 + k) * 256 + n];
    else         vn = Wkv[((size_t)l * 512 + k) * 512 + (n - 256)];
    g_Wn[idx] = vn;
}
// Edge fused Q|K: g_We[k][l*512 + n], n<256 -> Wq_bot, else K half of Wkv_bot.
__global__ void k_packe(const float* __restrict__ Wq, const float* __restrict__ Wkv) {
    const int idx = blockIdx.x * 256 + threadIdx.x;
    if (idx >= LLAYERS * 256 * 512) return;
    const int l = idx / (256 * 512);
    const int rem = idx - l * 256 * 512;
    const int k = rem / 512, n = rem - k * 512;
    float v;
    if (n < 256) v = Wq[((size_t)l * 512 + 256 + k) * 256 + n];
    else         v = Wkv[((size_t)l * 512 + 256 + k) * 512 + (n - 256)];
    g_We[(size_t)k * 2048 + l * 512 + n] = v;
}
// Block-diagonal edge V weights: g_WvBD[l][h*256+k][h*64+j] = Wkv_bot_V[k][h*64+j].
__global__ void k_packvbd(const float* __restrict__ Wkv) {
    const int idx = blockIdx.x * 256 + threadIdx.x;
    if (idx >= LLAYERS * 1024 * 256) return;
    const int l = idx / (1024 * 256);
    const int rem = idx - l * 1024 * 256;
    const int r = rem / 256, c = rem - r * 256;   // r = h*256 + k, c = out dim
    const int h = r >> 8, k = r & 255;
    float v = 0.f;
    if ((c >> 6) == h) v = Wkv[((size_t)l * 512 + 256 + k) * 512 + 256 + c];
    g_WvBD[idx] = v;
}
__global__ void k_packb(const float* __restrict__ bq, const float* __restrict__ bkv) {
    const int idx = blockIdx.x * 256 + threadIdx.x;
    if (idx >= LLAYERS * 768) return;
    const int l = idx / 768, n = idx - l * 768;
    g_bqkv[idx] = (n < 256) ? bq[l * 256 + n] : bkv[l * 512 + (n - 256)];
}

// ---------------- front-end feature kernels ----------------
__global__ void k_lfeat(const float* __restrict__ lat) {
    const int t = threadIdx.x;
    if (t >= BB * 6) return;
    const int b = t / 6, u = t % 6;
    const int r6[6] = {0, 0, 0, 1, 1, 2};
    const int c6[6] = {0, 1, 2, 1, 2, 2};
    float s = 0.f;
#pragma unroll
    for (int i = 0; i < 3; i++)
        s += lat[b * 9 + i * 3 + r6[u]] * lat[b * 9 + i * 3 + c6[u]];
    g_lfeat[t] = s;
}

__global__ void k_xnode(const int* __restrict__ types, const int* __restrict__ bids,
                        const float* __restrict__ emb) {
    const int idx = blockIdx.x * blockDim.x + threadIdx.x;
    if (idx >= NN * KPAD_NODE) return;
    const int n = idx / KPAD_NODE, k = idx - n * KPAD_NODE;
    float v = 0.f;
    if (k < 256)      v = emb[(size_t)types[n] * 256 + k];
    else if (k < 262) v = g_lfeat[bids[n] * 6 + (k - 256)];
    g_Xnode[idx] = v;
}

// Fourier edge features via rotation recurrence; fp16 output, padded to 608 with zeros.
__global__ void k_edgefeat(const float* __restrict__ frac, const float* __restrict__ shifts,
                           const int* __restrict__ src, const int* __restrict__ dst) {
    __shared__ float sh[16 * 600];
    const int e0 = blockIdx.x * 16;
    const int t = threadIdx.x;  // 128 threads
    if (t < 48) {
        const int el = t & 15;
        const int c = t >> 4;
        const int e = e0 + el;
        if (e < EE) {
            float d = frac[dst[e] * 3 + c] - frac[src[e] * 3 + c] + shifts[e * 3 + c];
            d -= floorf(d);
            const float theta = 6.2831853071795864769f * d;
            float st, ct;
            sincosf(theta, &st, &ct);
            float s = 0.f, cc = 1.f;
            float* row = sh + el * 600;
            for (int f = 0; f < 100; f++) {
                row[c * 100 + f] = s;
                row[300 + c * 100 + f] = cc;
                const float ns = fmaf(s, ct, cc * st);
                cc = fmaf(cc, ct, -s * st);
                s = ns;
            }
        }
    }
    __syncthreads();
    const int nrows = min(16, EE - e0);
    const int tot = nrows * KPAD_EDGE;
    for (int i = t; i < tot; i += 128) {
        const int r = i / KPAD_EDGE, c = i - r * KPAD_EDGE;
        g_XedgeH[(size_t)e0 * KPAD_EDGE + i] = __float2half((c < 600) ? sh[r * 600 + c] : 0.f);
    }
}

// ---------------- CSR build (edges grouped by src) ----------------
__global__ void k_hist(const int* __restrict__ src) {
    const int e = blockIdx.x * blockDim.x + threadIdx.x;
    if (e >= EE) return;
    atomicAdd(&g_deg[src[e]], 1);
}

__global__ void k_scan() {
    __shared__ int sh[1024];
    const int t = threadIdx.x;
    int local[8];
    int sum = 0;
#pragma unroll
    for (int j = 0; j < 8; j++) {
        const int idx = t * 8 + j;
        const int v = (idx < NN) ? g_deg[idx] : 0;
        local[j] = sum;
        sum += v;
    }
    sh[t] = sum;
    __syncthreads();
    for (int off = 1; off < 1024; off <<= 1) {
        const int v = (t >= off) ? sh[t - off] : 0;
        __syncthreads();
        sh[t] += v;
        __syncthreads();
    }
    const int base = (t == 0) ? 0 : sh[t - 1];
#pragma unroll
    for (int j = 0; j < 8; j++) {
        const int idx = t * 8 + j;
        if (idx < NN) g_rowptr[idx] = base + local[j];
    }
    if (t == 1023) g_rowptr[NN] = sh[1023];
}

__global__ void k_scatter(const int* __restrict__ src) {
    const int e = blockIdx.x * blockDim.x + threadIdx.x;
    if (e >= EE) return;
    const int slot = atomicAdd(&g_pos[src[e]], 1);
    g_order[slot] = e;
}

// ---------------- attention kernels ----------------
// QKVn layout: [Q|K|V] fp32 stride 768. QKeH: per-layer [Q|K] fp16 at offset l*512, stride 2048.
__global__ void k_scores(const int* __restrict__ src, const int* __restrict__ dst, int loff) {
    const int w = (blockIdx.x * blockDim.x + threadIdx.x) >> 5;
    const int lane = threadIdx.x & 31;
    if (w >= EE) return;
    const int s = src[w], d = dst[w];
    const int off = lane * 8;
    const float4* qn = (const float4*)(g_QKVn + (size_t)s * 768 + off);
    const float4* kn = (const float4*)(g_QKVn + (size_t)d * 768 + 256 + off);
    const uint4 qe4 = *(const uint4*)(g_QKeH + (size_t)w * 2048 + loff + off);
    const uint4 ke4 = *(const uint4*)(g_QKeH + (size_t)w * 2048 + loff + 256 + off);
    float qe[8], ke[8];
    {
        const __half2* q2 = (const __half2*)&qe4;
        const __half2* k2 = (const __half2*)&ke4;
#pragma unroll
        for (int p = 0; p < 4; p++) {
            const float2 fq = __half22float2(q2[p]);
            const float2 fk = __half22float2(k2[p]);
            qe[2 * p] = fq.x; qe[2 * p + 1] = fq.y;
            ke[2 * p] = fk.x; ke[2 * p + 1] = fk.y;
        }
    }
    float sum = 0.f;
#pragma unroll
    for (int p = 0; p < 2; p++) {
        const float4 a = qn[p], x = kn[p];
        sum += (a.x + qe[4 * p + 0]) * (x.x + ke[4 * p + 0])
             + (a.y + qe[4 * p + 1]) * (x.y + ke[4 * p + 1])
             + (a.z + qe[4 * p + 2]) * (x.z + ke[4 * p + 2])
             + (a.w + qe[4 * p + 3]) * (x.w + ke[4 * p + 3]);
    }
    sum += __shfl_down_sync(0xffffffffu, sum, 4);
    sum += __shfl_down_sync(0xffffffffu, sum, 2);
    sum += __shfl_down_sync(0xffffffffu, sum, 1);
    if ((lane & 7) == 0) g_sc[(size_t)w * 4 + (lane >> 3)] = sum * 0.125f;
}

__global__ void k_softmax() {
    const int w = (blockIdx.x * blockDim.x + threadIdx.x) >> 5;
    const int lane = threadIdx.x & 31;
    if (w >= NN) return;
    const int beg = g_rowptr[w], end = g_rowptr[w + 1];
    float m0 = -1e30f, m1 = -1e30f, m2 = -1e30f, m3 = -1e30f;
    for (int i = beg + lane; i < end; i += 32) {
        const float4 s = *(const float4*)(g_sc + (size_t)g_order[i] * 4);
        m0 = fmaxf(m0, s.x); m1 = fmaxf(m1, s.y);
        m2 = fmaxf(m2, s.z); m3 = fmaxf(m3, s.w);
    }
    m0 = wredmax(m0); m1 = wredmax(m1); m2 = wredmax(m2); m3 = wredmax(m3);
    float d0 = 0.f, d1 = 0.f, d2 = 0.f, d3 = 0.f;
    for (int i = beg + lane; i < end; i += 32) {
        const int e = g_order[i];
        float4 s = *(const float4*)(g_sc + (size_t)e * 4);
        s.x = __expf(s.x - m0); s.y = __expf(s.y - m1);
        s.z = __expf(s.z - m2); s.w = __expf(s.w - m3);
        *(float4*)(g_sc + (size_t)e * 4) = s;
        d0 += s.x; d1 += s.y; d2 += s.z; d3 += s.w;
    }
    d0 = wredsum(d0); d1 = wredsum(d1); d2 = wredsum(d2); d3 = wredsum(d3);
    if (lane == 0) {
        float4 iv;
        iv.x = (d0 > 0.f) ? 1.f / d0 : 0.f;
        iv.y = (d1 > 0.f) ? 1.f / d1 : 0.f;
        iv.z = (d2 > 0.f) ? 1.f / d2 : 0.f;
        iv.w = (d3 > 0.f) ? 1.f / d3 : 0.f;
        *(float4*)(g_invden + w * 4) = iv;
    }
}

// V-trick aggregation (warp per node, lane owns 8 dims):
//   A[dim]   = sum_e w[e, dim>>6] * Vn[dst][dim]        -> g_attn (fp32)
//   G[h,dim] = sum_e w[e, h]      * h_e[e][dim]         -> g_aggGH (fp16, N x 1024)
__global__ void k_agg(const int* __restrict__ dst) {
    const int w = (blockIdx.x * blockDim.x + threadIdx.x) >> 5;
    const int lane = threadIdx.x & 31;
    if (w >= NN) return;
    float accA[8];
    float accG[4][8];
#pragma unroll
    for (int j = 0; j < 8; j++) {
        accA[j] = 0.f;
#pragma unroll
        for (int h = 0; h < 4; h++) accG[h][j] = 0.f;
    }
    const float4 iv = *(const float4*)(g_invden + w * 4);
    const int beg = g_rowptr[w], end = g_rowptr[w + 1];
    for (int i = beg; i < end; i++) {
        const int e = g_order[i];
        const int d = dst[e];
        const float4 ex = *(const float4*)(g_sc + (size_t)e * 4);
        float wt[4];
        wt[0] = ex.x * iv.x; wt[1] = ex.y * iv.y;
        wt[2] = ex.z * iv.z; wt[3] = ex.w * iv.w;
        const float* vn = g_QKVn + (size_t)d * 768 + 512;
        const __half* hep = g_heH + (size_t)e * 256;
#pragma unroll
        for (int j = 0; j < 8; j++) {
            const int dim = lane + 32 * j;
            accA[j] = fmaf(wt[j >> 1], vn[dim], accA[j]);
            const float hv = __half2float(hep[dim]);
#pragma unroll
            for (int h = 0; h < 4; h++) accG[h][j] = fmaf(wt[h], hv, accG[h][j]);
        }
    }
#pragma unroll
    for (int j = 0; j < 8; j++) {
        const int dim = lane + 32 * j;
        g_attn[(size_t)w * 256 + dim] = accA[j];
#pragma unroll
        for (int h = 0; h < 4; h++)
            g_aggGH[(size_t)w * 1024 + h * 256 + dim] = __float2half(accG[h][j]);
    }
}

// h_n = LayerNorm(h_n + delta) * g + b   (warp per row)
__global__ void k_resln(const float* __restrict__ delta, const float* __restrict__ gam,
                        const float* __restrict__ bet) {
    const int w = (blockIdx.x * blockDim.x + threadIdx.x) >> 5;
    const int lane = threadIdx.x & 31;
    if (w >= NN) return;
    float x[8];
    float s = 0.f;
#pragma unroll
    for (int j = 0; j < 8; j++) {
        const int dim = lane + 32 * j;
        x[j] = g_hn[(size_t)w * 256 + dim] + delta[(size_t)w * 256 + dim];
        s += x[j];
    }
    s = wredsum(s);
    const float mu = s * (1.f / 256.f);
    float v = 0.f;
#pragma unroll
    for (int j = 0; j < 8; j++) {
        const float t = x[j] - mu;
        v += t * t;
    }
    v = wredsum(v);
    const float r = rsqrtf(v * (1.f / 256.f) + 1e-5f);
#pragma unroll
    for (int j = 0; j < 8; j++) {
        const int dim = lane + 32 * j;
        g_hn[(size_t)w * 256 + dim] = (x[j] - mu) * r * gam[dim] + bet[dim];
    }
}

// ---------------- launch ----------------
extern "C" void kernel_launch(void* const* d_in, const int* in_sizes, int n_in,
                              void* d_out, int out_size) {
    const int*   atom_types = (const int*)d_in[0];
    const float* lattices   = (const float*)d_in[1];
    const float* frac       = (const float*)d_in[2];
    const int*   eidx       = (const int*)d_in[3];
    const float* shifts     = (const float*)d_in[4];
    const int*   bids       = (const int*)d_in[5];
    const float* atom_emb   = (const float*)d_in[6];
    const float* node_W     = (const float*)d_in[7];
    const float* node_b     = (const float*)d_in[8];
    const float* edge_W     = (const float*)d_in[9];
    const float* edge_b     = (const float*)d_in[10];
    const float* Wq         = (const float*)d_in[11];
    const float* bq         = (const float*)d_in[12];
    const float* Wkv        = (const float*)d_in[13];
    const float* bkv        = (const float*)d_in[14];
    const float* Wo         = (const float*)d_in[15];
    const float* bo         = (const float*)d_in[16];
    const float* ln1_g      = (const float*)d_in[17];
    const float* ln1_b      = (const float*)d_in[18];
    const float* W1         = (const float*)d_in[19];
    const float* b1         = (const float*)d_in[20];
    const float* W2         = (const float*)d_in[21];
    const float* b2         = (const float*)d_in[22];
    const float* ln2_g      = (const float*)d_in[23];
    const float* ln2_b      = (const float*)d_in[24];
    const int* src = eidx;
    const int* dst = eidx + EE;

    float *pXnode, *phn, *pQKVn, *pattn, *pffn1, *ptmp;
    float *pWn, *pWe, *pWvBD, *pbqkv;
    __half *pXedgeH, *pheH, *pQKeH, *paggGH;
    int *pdeg, *prow, *ppos;
    cudaGetSymbolAddress((void**)&pXnode, g_Xnode);
    cudaGetSymbolAddress((void**)&pXedgeH, g_XedgeH);
    cudaGetSymbolAddress((void**)&phn, g_hn);
    cudaGetSymbolAddress((void**)&pheH, g_heH);
    cudaGetSymbolAddress((void**)&pQKVn, g_QKVn);
    cudaGetSymbolAddress((void**)&pQKeH, g_QKeH);
    cudaGetSymbolAddress((void**)&pattn, g_attn);
    cudaGetSymbolAddress((void**)&paggGH, g_aggGH);
    cudaGetSymbolAddress((void**)&pffn1, g_ffn1);
    cudaGetSymbolAddress((void**)&ptmp, g_tmp);
    cudaGetSymbolAddress((void**)&pWn, g_Wn);
    cudaGetSymbolAddress((void**)&pWe, g_We);
    cudaGetSymbolAddress((void**)&pWvBD, g_WvBD);
    cudaGetSymbolAddress((void**)&pbqkv, g_bqkv);
    cudaGetSymbolAddress((void**)&pdeg, g_deg);
    cudaGetSymbolAddress((void**)&prow, g_rowptr);
    cudaGetSymbolAddress((void**)&ppos, g_pos);

    const int MB_N = (NN + 127) / 128;   // 63
    const int MB_E = (EE + 127) / 128;   // 1563
    const float* nul = (const float*)0;

    // ---- weight packing ----
    k_pack<<<(LLAYERS * 256 * 768 + 255) / 256, 256>>>(Wq, Wkv);
    k_packe<<<(LLAYERS * 256 * 512 + 255) / 256, 256>>>(Wq, Wkv);
    k_packvbd<<<(LLAYERS * 1024 * 256 + 255) / 256, 256>>>(Wkv);
    k_packb<<<(LLAYERS * 768 + 255) / 256, 256>>>(bq, bkv);

    // ---- front end ----
    k_lfeat<<<1, 96>>>(lattices);
    k_xnode<<<(NN * KPAD_NODE + 255) / 256, 256>>>(atom_types, bids, atom_emb);
    tgemm_k<0, 0, 0><<<dim3(2, MB_N), 256>>>(NN, 262, pXnode, KPAD_NODE, node_W, 256, node_b, nul, phn, 256);
    k_edgefeat<<<(EE + 15) / 16, 128>>>(frac, shifts, src, dst);
    tgemm_k<0, 1, 1><<<dim3(2, MB_E), 256>>>(EE, 600, pXedgeH, KPAD_EDGE, edge_W, 256, edge_b, nul, pheH, 256);

    // ---- CSR (src-grouped) ----
    cudaMemsetAsync(pdeg, 0, NN * sizeof(int));
    k_hist<<<(EE + 255) / 256, 256>>>(src);
    k_scan<<<1, 1024>>>();
    cudaMemcpyAsync(ppos, prow, NN * sizeof(int), cudaMemcpyDeviceToDevice);
    k_scatter<<<(EE + 255) / 256, 256>>>(src);

    // ---- fused 4-layer edge Q|K projection: E x 256 @ 256 x 2048 (A fp16, C fp16) ----
    tgemm_k<0, 1, 1><<<dim3(16, MB_E), 256>>>(EE, 256, pheH, 256, pWe, 2048, nul, nul, pQKeH, 2048);

    // ---- transformer layers ----
    for (int i = 0; i < LLAYERS; i++) {
        const float* wn = pWn + (size_t)i * 256 * 768;
        const int loff = i * 512;
        // node QKV projection (depends on current h_n)
        tgemm_k<0, 0, 0><<<dim3(6, MB_N), 256>>>(NN, 256, phn, 256, wn, 768, pbqkv + i * 768, nul, pQKVn, 768);
        // attention
        k_scores<<<(EE + 7) / 8, 256>>>(src, dst, loff);
        k_softmax<<<(NN + 7) / 8, 256>>>();
        k_agg<<<(NN + 7) / 8, 256>>>(dst);
        // attn = A + G @ WvBD  (in place on g_attn; A fp16 input)
        tgemm_k<0, 1, 0><<<dim3(2, MB_N), 256>>>(NN, 1024, paggGH, 1024, pWvBD + (size_t)i * 1024 * 256, 256, nul, pattn, pattn, 256);
        tgemm_k<0, 0, 0><<<dim3(2, MB_N), 256>>>(NN, 256, pattn, 256, Wo + (size_t)i * 256 * 256, 256, bo + i * 256, nul, ptmp, 256);
        k_resln<<<(NN + 7) / 8, 256>>>(ptmp, ln1_g + i * 256, ln1_b + i * 256);
        // FFN
        tgemm_k<1, 0, 0><<<dim3(8, MB_N), 256>>>(NN, 256, phn, 256, W1 + (size_t)i * 256 * 1024, 1024, b1 + i * 1024, nul, pffn1, 1024);
        tgemm_k<0, 0, 0><<<dim3(2, MB_N), 256>>>(NN, 1024, pffn1, 1024, W2 + (size_t)i * 1024 * 256, 256, b2 + i * 256, nul, ptmp, 256);
        k_resln<<<(NN + 7) / 8, 256>>>(ptmp, ln2_g + i * 256, ln2_b + i * 256);
    }

    cudaMemcpyAsync(d_out, phn, (size_t)NN * 256 * sizeof(float), cudaMemcpyDeviceToDevice);
}

// round 17
// speedup vs baseline: 1.4789x; 1.4789x over previous
#include <cuda_runtime.h>
#include <cuda_fp16.h>
#include <math.h>
#include <stdint.h>

// Problem constants
#define NN 8000
#define EE 200000
#define BB 16
#define DD 256
#define LLAYERS 4

#define KPAD_NODE 272   // 262 rounded up to 16
#define KPAD_EDGE 608   // 600 rounded up to 16

// ---------------- scratch (static device globals; no allocation) ----------------
__device__ float g_lfeat[BB * 6];
__device__ float g_Xnode[NN * KPAD_NODE];
__device__ float g_hn[NN * DD];
__device__ float g_Xedge[(size_t)EE * KPAD_EDGE];
__device__ __half g_heH[(size_t)EE * DD];          // fp16 storage
__device__ float g_QKVn[(size_t)NN * 768];
__device__ __half g_QKeH[(size_t)EE * 2048];       // 4 layers x [Q|K], fp16, stride 2048
__device__ float g_sc[(size_t)EE * 4];
__device__ float g_invden[NN * 4];
__device__ float g_attn[NN * DD];
__device__ __half g_aggGH[(size_t)NN * 1024];      // fp16 storage
__device__ float g_ffn1[NN * 1024];
__device__ float g_tmp[NN * DD];
__device__ float g_Wn[LLAYERS * 256 * 768];
__device__ float g_We[256 * 2048];
__device__ float g_WvBD[LLAYERS * 1024 * 256];
__device__ float g_bqkv[LLAYERS * 768];
__device__ int   g_deg[NN];
__device__ int   g_rowptr[NN + 1];
__device__ int   g_pos[NN];
__device__ int   g_order[EE];

// ---------------- helpers ----------------
__device__ __forceinline__ float gelu_f(float x) {
    return 0.5f * x * (1.0f + erff(x * 0.70710678118654752f));
}
__device__ __forceinline__ float wredsum(float v) {
    for (int o = 16; o > 0; o >>= 1) v += __shfl_xor_sync(0xffffffffu, v, o);
    return v;
}
__device__ __forceinline__ float wredmax(float v) {
    for (int o = 16; o > 0; o >>= 1) v = fmaxf(v, __shfl_xor_sync(0xffffffffu, v, o));
    return v;
}
__device__ __forceinline__ uint32_t f2tf(float x) {
    uint32_t r;
    asm("cvt.rna.tf32.f32 %0, %1;" : "=r"(r) : "f"(x));
    return r;
}

// ---------------- tf32 tensor-core GEMM: C = act(A @ B + bias [+ res]) ----------------
// Tiles: BM=128 BN=128 BK=16. 256 threads = 8 warps (4 along M x 2 along N).
// Warp tile 32x64 via mma.sync.m16n8k8 (proven round-4/6 config).
// AH: A elements are __half (else float). OH: C elements are __half (else float).
// Requirements: lda % 4 == 0; A zero-padded to kiters*16 cols; N % 128 == 0.
#define SSTR 136   // 128 + 8 padding -> conflict-free fragment reads

template <int ACT, int AH, int OH>
__global__ void __launch_bounds__(256) tgemm_k(
    int M, int K,
    const void* __restrict__ Ap, int lda,
    const float* __restrict__ B, int ldb,
    const float* __restrict__ bias,
    const float* __restrict__ res,
    void* __restrict__ Cp, int ldc)
{
    __shared__ uint32_t As[2][16][SSTR];
    __shared__ uint32_t Bs[2][16][SSTR];
    const float*  Af = (const float*)Ap;
    const __half* Ah = (const __half*)Ap;
    const int tid = threadIdx.x;
    const int bn = blockIdx.x * 128;
    const int bm = blockIdx.y * 128;
    const int warp = tid >> 5, lane = tid & 31;
    const int wm = (warp & 3) * 32;
    const int wn = (warp >> 2) * 64;
    const int grp = lane >> 2, t4 = lane & 3;

    float acc[2][8][4];
#pragma unroll
    for (int i = 0; i < 2; i++)
#pragma unroll
        for (int j = 0; j < 8; j++)
#pragma unroll
            for (int q = 0; q < 4; q++) acc[i][j][q] = 0.f;

    const int kiters = (K + 15) >> 4;

    float4 ar[2], br[2];

    auto loadg = [&](int k0) {
#pragma unroll
        for (int l = 0; l < 2; l++) {
            const int idx = tid + l * 256;
            const int r = idx >> 2, cg = idx & 3;           // A: 128 rows x 4 k-groups
            const int gm = bm + r;
            if (gm < M) {
                if (AH) {
                    const uint2 u = *(const uint2*)(Ah + (size_t)gm * lda + k0 + cg * 4);
                    const float2 f0 = __half22float2(*(const __half2*)&u.x);
                    const float2 f1 = __half22float2(*(const __half2*)&u.y);
                    ar[l] = make_float4(f0.x, f0.y, f1.x, f1.y);
                } else {
                    ar[l] = *(const float4*)(Af + (size_t)gm * lda + k0 + cg * 4);
                }
            } else ar[l] = make_float4(0.f, 0.f, 0.f, 0.f);
            const int row = idx >> 5, c4 = idx & 31;        // B: 16 rows x 32 col-groups
            const int gk = k0 + row;
            if (gk < K) br[l] = *(const float4*)(B + (size_t)gk * ldb + bn + c4 * 4);
            else        br[l] = make_float4(0.f, 0.f, 0.f, 0.f);
        }
    };
    auto store_s = [&](int buf) {
#pragma unroll
        for (int l = 0; l < 2; l++) {
            const int idx = tid + l * 256;
            const int r = idx >> 2, cg = idx & 3;
            As[buf][cg * 4 + 0][r] = f2tf(ar[l].x);
            As[buf][cg * 4 + 1][r] = f2tf(ar[l].y);
            As[buf][cg * 4 + 2][r] = f2tf(ar[l].z);
            As[buf][cg * 4 + 3][r] = f2tf(ar[l].w);
            const int row = idx >> 5, c4 = idx & 31;
            uint32_t* p = &Bs[buf][row][c4 * 4];
            p[0] = f2tf(br[l].x); p[1] = f2tf(br[l].y);
            p[2] = f2tf(br[l].z); p[3] = f2tf(br[l].w);
        }
    };
    auto compute = [&](int buf) {
#pragma unroll
        for (int ks = 0; ks < 2; ks++) {
            uint32_t af[2][4], bf[8][2];
#pragma unroll
            for (int mb = 0; mb < 2; mb++) {
                const int m0 = wm + mb * 16;
                af[mb][0] = As[buf][ks * 8 + t4][m0 + grp];
                af[mb][1] = As[buf][ks * 8 + t4][m0 + grp + 8];
                af[mb][2] = As[buf][ks * 8 + t4 + 4][m0 + grp];
                af[mb][3] = As[buf][ks * 8 + t4 + 4][m0 + grp + 8];
            }
#pragma unroll
            for (int nb = 0; nb < 8; nb++) {
                const int n0 = wn + nb * 8;
                bf[nb][0] = Bs[buf][ks * 8 + t4][n0 + grp];
                bf[nb][1] = Bs[buf][ks * 8 + t4 + 4][n0 + grp];
            }
#pragma unroll
            for (int mb = 0; mb < 2; mb++)
#pragma unroll
                for (int nb = 0; nb < 8; nb++) {
                    float* c = acc[mb][nb];
                    asm volatile(
                        "mma.sync.aligned.m16n8k8.row.col.f32.tf32.tf32.f32 "
                        "{%0,%1,%2,%3}, {%4,%5,%6,%7}, {%8,%9}, {%0,%1,%2,%3};\n"
                        : "+f"(c[0]), "+f"(c[1]), "+f"(c[2]), "+f"(c[3])
                        : "r"(af[mb][0]), "r"(af[mb][1]), "r"(af[mb][2]), "r"(af[mb][3]),
                          "r"(bf[nb][0]), "r"(bf[nb][1]));
                }
        }
    };

    loadg(0);
    store_s(0);
    __syncthreads();
    int buf = 0;
    for (int ki = 1; ki < kiters; ki++) {
        loadg(ki * 16);
        compute(buf);
        store_s(buf ^ 1);
        __syncthreads();
        buf ^= 1;
    }
    compute(buf);

    // ---- epilogue ----
#pragma unroll
    for (int mb = 0; mb < 2; mb++) {
        const int r0 = bm + wm + mb * 16 + grp;
#pragma unroll
        for (int nb = 0; nb < 8; nb++) {
            const int gn = bn + wn + nb * 8 + t4 * 2;
            float b0v = 0.f, b1v = 0.f;
            if (bias) { b0v = bias[gn]; b1v = bias[gn + 1]; }
            float v0 = acc[mb][nb][0] + b0v, v1 = acc[mb][nb][1] + b1v;
            float v2 = acc[mb][nb][2] + b0v, v3 = acc[mb][nb][3] + b1v;
            if (res) {
                if (r0 < M) {
                    v0 += res[(size_t)r0 * ldc + gn];
                    v1 += res[(size_t)r0 * ldc + gn + 1];
                }
                if (r0 + 8 < M) {
                    v2 += res[(size_t)(r0 + 8) * ldc + gn];
                    v3 += res[(size_t)(r0 + 8) * ldc + gn + 1];
                }
            }
            if (ACT == 1) { v0 = gelu_f(v0); v1 = gelu_f(v1); v2 = gelu_f(v2); v3 = gelu_f(v3); }
            if (OH) {
                __half* C = (__half*)Cp;
                if (r0 < M)     *(__half2*)(C + (size_t)r0 * ldc + gn)       = __floats2half2_rn(v0, v1);
                if (r0 + 8 < M) *(__half2*)(C + (size_t)(r0 + 8) * ldc + gn) = __floats2half2_rn(v2, v3);
            } else {
                float* C = (float*)Cp;
                if (r0 < M)     *(float2*)(C + (size_t)r0 * ldc + gn)       = make_float2(v0, v1);
                if (r0 + 8 < M) *(float2*)(C + (size_t)(r0 + 8) * ldc + gn) = make_float2(v2, v3);
            }
        }
    }
}

// ---------------- weight packing ----------------
// Node: g_Wn[l][k][n768] = [Wq_top | Wkv_top] (Q,K,V).
__global__ void k_pack(const float* __restrict__ Wq, const float* __restrict__ Wkv) {
    const int idx = blockIdx.x * 256 + threadIdx.x;
    if (idx >= LLAYERS * 256 * 768) return;
    const int l = idx / (256 * 768);
    const int rem = idx - l * 256 * 768;
    const int k = rem / 768, n = rem - k * 768;
    float vn;
    if (n < 256) vn = Wq[((size_t)l * 512 + k) * 256 + n];
    else         vn = Wkv[((size_t)l * 512 + k) * 512 + (n - 256)];
    g_Wn[idx] = vn;
}
// Edge fused Q|K: g_We[k][l*512 + n], n<256 -> Wq_bot, else K half of Wkv_bot.
__global__ void k_packe(const float* __restrict__ Wq, const float* __restrict__ Wkv) {
    const int idx = blockIdx.x * 256 + threadIdx.x;
    if (idx >= LLAYERS * 256 * 512) return;
    const int l = idx / (256 * 512);
    const int rem = idx - l * 256 * 512;
    const int k = rem / 512, n = rem - k * 512;
    float v;
    if (n < 256) v = Wq[((size_t)l * 512 + 256 + k) * 256 + n];
    else         v = Wkv[((size_t)l * 512 + 256 + k) * 512 + (n - 256)];
    g_We[(size_t)k * 2048 + l * 512 + n] = v;
}
// Block-diagonal edge V weights: g_WvBD[l][h*256+k][h*64+j] = Wkv_bot_V[k][h*64+j].
__global__ void k_packvbd(const float* __restrict__ Wkv) {
    const int idx = blockIdx.x * 256 + threadIdx.x;
    if (idx >= LLAYERS * 1024 * 256) return;
    const int l = idx / (1024 * 256);
    const int rem = idx - l * 1024 * 256;
    const int r = rem / 256, c = rem - r * 256;   // r = h*256 + k, c = out dim
    const int h = r >> 8, k = r & 255;
    float v = 0.f;
    if ((c >> 6) == h) v = Wkv[((size_t)l * 512 + 256 + k) * 512 + 256 + c];
    g_WvBD[idx] = v;
}
__global__ void k_packb(const float* __restrict__ bq, const float* __restrict__ bkv) {
    const int idx = blockIdx.x * 256 + threadIdx.x;
    if (idx >= LLAYERS * 768) return;
    const int l = idx / 768, n = idx - l * 768;
    g_bqkv[idx] = (n < 256) ? bq[l * 256 + n] : bkv[l * 512 + (n - 256)];
}

// ---------------- front-end feature kernels ----------------
__global__ void k_lfeat(const float* __restrict__ lat) {
    const int t = threadIdx.x;
    if (t >= BB * 6) return;
    const int b = t / 6, u = t % 6;
    const int r6[6] = {0, 0, 0, 1, 1, 2};
    const int c6[6] = {0, 1, 2, 1, 2, 2};
    float s = 0.f;
#pragma unroll
    for (int i = 0; i < 3; i++)
        s += lat[b * 9 + i * 3 + r6[u]] * lat[b * 9 + i * 3 + c6[u]];
    g_lfeat[t] = s;
}

__global__ void k_xnode(const int* __restrict__ types, const int* __restrict__ bids,
                        const float* __restrict__ emb) {
    const int idx = blockIdx.x * blockDim.x + threadIdx.x;
    if (idx >= NN * KPAD_NODE) return;
    const int n = idx / KPAD_NODE, k = idx - n * KPAD_NODE;
    float v = 0.f;
    if (k < 256)      v = emb[(size_t)types[n] * 256 + k];
    else if (k < 262) v = g_lfeat[bids[n] * 6 + (k - 256)];
    g_Xnode[idx] = v;
}

// Fourier edge features via rotation recurrence; rows padded to 608 with zeros.
__global__ void k_edgefeat(const float* __restrict__ frac, const float* __restrict__ shifts,
                           const int* __restrict__ src, const int* __restrict__ dst) {
    __shared__ float sh[16 * 600];
    const int e0 = blockIdx.x * 16;
    const int t = threadIdx.x;  // 128 threads
    if (t < 48) {
        const int el = t & 15;
        const int c = t >> 4;
        const int e = e0 + el;
        if (e < EE) {
            float d = frac[dst[e] * 3 + c] - frac[src[e] * 3 + c] + shifts[e * 3 + c];
            d -= floorf(d);
            const float theta = 6.2831853071795864769f * d;
            float st, ct;
            sincosf(theta, &st, &ct);
            float s = 0.f, cc = 1.f;
            float* row = sh + el * 600;
            for (int f = 0; f < 100; f++) {
                row[c * 100 + f] = s;
                row[300 + c * 100 + f] = cc;
                const float ns = fmaf(s, ct, cc * st);
                cc = fmaf(cc, ct, -s * st);
                s = ns;
            }
        }
    }
    __syncthreads();
    const int nrows = min(16, EE - e0);
    const int tot = nrows * KPAD_EDGE;
    for (int i = t; i < tot; i += 128) {
        const int r = i / KPAD_EDGE, c = i - r * KPAD_EDGE;
        g_Xedge[(size_t)e0 * KPAD_EDGE + i] = (c < 600) ? sh[r * 600 + c] : 0.f;
    }
}

// ---------------- CSR build (edges grouped by src) ----------------
__global__ void k_hist(const int* __restrict__ src) {
    const int e = blockIdx.x * blockDim.x + threadIdx.x;
    if (e >= EE) return;
    atomicAdd(&g_deg[src[e]], 1);
}

__global__ void k_scan() {
    __shared__ int sh[1024];
    const int t = threadIdx.x;
    int local[8];
    int sum = 0;
#pragma unroll
    for (int j = 0; j < 8; j++) {
        const int idx = t * 8 + j;
        const int v = (idx < NN) ? g_deg[idx] : 0;
        local[j] = sum;
        sum += v;
    }
    sh[t] = sum;
    __syncthreads();
    for (int off = 1; off < 1024; off <<= 1) {
        const int v = (t >= off) ? sh[t - off] : 0;
        __syncthreads();
        sh[t] += v;
        __syncthreads();
    }
    const int base = (t == 0) ? 0 : sh[t - 1];
#pragma unroll
    for (int j = 0; j < 8; j++) {
        const int idx = t * 8 + j;
        if (idx < NN) g_rowptr[idx] = base + local[j];
    }
    if (t == 1023) g_rowptr[NN] = sh[1023];
}

__global__ void k_scatter(const int* __restrict__ src) {
    const int e = blockIdx.x * blockDim.x + threadIdx.x;
    if (e >= EE) return;
    const int slot = atomicAdd(&g_pos[src[e]], 1);
    g_order[slot] = e;
}

// ---------------- attention kernels ----------------
// QKVn layout: [Q|K|V] fp32 stride 768. QKeH: per-layer [Q|K] fp16 at offset l*512, stride 2048.
__global__ void k_scores(const int* __restrict__ src, const int* __restrict__ dst, int loff) {
    const int w = (blockIdx.x * blockDim.x + threadIdx.x) >> 5;
    const int lane = threadIdx.x & 31;
    if (w >= EE) return;
    const int s = src[w], d = dst[w];
    const int off = lane * 8;
    const float4* qn = (const float4*)(g_QKVn + (size_t)s * 768 + off);
    const float4* kn = (const float4*)(g_QKVn + (size_t)d * 768 + 256 + off);
    const uint4 qe4 = *(const uint4*)(g_QKeH + (size_t)w * 2048 + loff + off);
    const uint4 ke4 = *(const uint4*)(g_QKeH + (size_t)w * 2048 + loff + 256 + off);
    float qe[8], ke[8];
    {
        const __half2* q2 = (const __half2*)&qe4;
        const __half2* k2 = (const __half2*)&ke4;
#pragma unroll
        for (int p = 0; p < 4; p++) {
            const float2 fq = __half22float2(q2[p]);
            const float2 fk = __half22float2(k2[p]);
            qe[2 * p] = fq.x; qe[2 * p + 1] = fq.y;
            ke[2 * p] = fk.x; ke[2 * p + 1] = fk.y;
        }
    }
    float sum = 0.f;
#pragma unroll
    for (int p = 0; p < 2; p++) {
        const float4 a = qn[p], x = kn[p];
        sum += (a.x + qe[4 * p + 0]) * (x.x + ke[4 * p + 0])
             + (a.y + qe[4 * p + 1]) * (x.y + ke[4 * p + 1])
             + (a.z + qe[4 * p + 2]) * (x.z + ke[4 * p + 2])
             + (a.w + qe[4 * p + 3]) * (x.w + ke[4 * p + 3]);
    }
    sum += __shfl_down_sync(0xffffffffu, sum, 4);
    sum += __shfl_down_sync(0xffffffffu, sum, 2);
    sum += __shfl_down_sync(0xffffffffu, sum, 1);
    if ((lane & 7) == 0) g_sc[(size_t)w * 4 + (lane >> 3)] = sum * 0.125f;
}

__global__ void k_softmax() {
    const int w = (blockIdx.x * blockDim.x + threadIdx.x) >> 5;
    const int lane = threadIdx.x & 31;
    if (w >= NN) return;
    const int beg = g_rowptr[w], end = g_rowptr[w + 1];
    float m0 = -1e30f, m1 = -1e30f, m2 = -1e30f, m3 = -1e30f;
    for (int i = beg + lane; i < end; i += 32) {
        const float4 s = *(const float4*)(g_sc + (size_t)g_order[i] * 4);
        m0 = fmaxf(m0, s.x); m1 = fmaxf(m1, s.y);
        m2 = fmaxf(m2, s.z); m3 = fmaxf(m3, s.w);
    }
    m0 = wredmax(m0); m1 = wredmax(m1); m2 = wredmax(m2); m3 = wredmax(m3);
    float d0 = 0.f, d1 = 0.f, d2 = 0.f, d3 = 0.f;
    for (int i = beg + lane; i < end; i += 32) {
        const int e = g_order[i];
        float4 s = *(const float4*)(g_sc + (size_t)e * 4);
        s.x = __expf(s.x - m0); s.y = __expf(s.y - m1);
        s.z = __expf(s.z - m2); s.w = __expf(s.w - m3);
        *(float4*)(g_sc + (size_t)e * 4) = s;
        d0 += s.x; d1 += s.y; d2 += s.z; d3 += s.w;
    }
    d0 = wredsum(d0); d1 = wredsum(d1); d2 = wredsum(d2); d3 = wredsum(d3);
    if (lane == 0) {
        float4 iv;
        iv.x = (d0 > 0.f) ? 1.f / d0 : 0.f;
        iv.y = (d1 > 0.f) ? 1.f / d1 : 0.f;
        iv.z = (d2 > 0.f) ? 1.f / d2 : 0.f;
        iv.w = (d3 > 0.f) ? 1.f / d3 : 0.f;
        *(float4*)(g_invden + w * 4) = iv;
    }
}

// V-trick aggregation (warp per node, lane owns 8 dims):
//   A[dim]   = sum_e w[e, dim>>6] * Vn[dst][dim]        -> g_attn (fp32)
//   G[h,dim] = sum_e w[e, h]      * h_e[e][dim]         -> g_aggGH (fp16, N x 1024)
__global__ void k_agg(const int* __restrict__ dst) {
    const int w = (blockIdx.x * blockDim.x + threadIdx.x) >> 5;
    const int lane = threadIdx.x & 31;
    if (w >= NN) return;
    float accA[8];
    float accG[4][8];
#pragma unroll
    for (int j = 0; j < 8; j++) {
        accA[j] = 0.f;
#pragma unroll
        for (int h = 0; h < 4; h++) accG[h][j] = 0.f;
    }
    const float4 iv = *(const float4*)(g_invden + w * 4);
    const int beg = g_rowptr[w], end = g_rowptr[w + 1];
    for (int i = beg; i < end; i++) {
        const int e = g_order[i];
        const int d = dst[e];
        const float4 ex = *(const float4*)(g_sc + (size_t)e * 4);
        float wt[4];
        wt[0] = ex.x * iv.x; wt[1] = ex.y * iv.y;
        wt[2] = ex.z * iv.z; wt[3] = ex.w * iv.w;
        const float* vn = g_QKVn + (size_t)d * 768 + 512;
        const __half* hep = g_heH + (size_t)e * 256;
#pragma unroll
        for (int j = 0; j < 8; j++) {
            const int dim = lane + 32 * j;
            accA[j] = fmaf(wt[j >> 1], vn[dim], accA[j]);
            const float hv = __half2float(hep[dim]);
#pragma unroll
            for (int h = 0; h < 4; h++) accG[h][j] = fmaf(wt[h], hv, accG[h][j]);
        }
    }
#pragma unroll
    for (int j = 0; j < 8; j++) {
        const int dim = lane + 32 * j;
        g_attn[(size_t)w * 256 + dim] = accA[j];
#pragma unroll
        for (int h = 0; h < 4; h++)
            g_aggGH[(size_t)w * 1024 + h * 256 + dim] = __float2half(accG[h][j]);
    }
}

// h_n = LayerNorm(h_n + delta) * g + b   (warp per row)
__global__ void k_resln(const float* __restrict__ delta, const float* __restrict__ gam,
                        const float* __restrict__ bet) {
    const int w = (blockIdx.x * blockDim.x + threadIdx.x) >> 5;
    const int lane = threadIdx.x & 31;
    if (w >= NN) return;
    float x[8];
    float s = 0.f;
#pragma unroll
    for (int j = 0; j < 8; j++) {
        const int dim = lane + 32 * j;
        x[j] = g_hn[(size_t)w * 256 + dim] + delta[(size_t)w * 256 + dim];
        s += x[j];
    }
    s = wredsum(s);
    const float mu = s * (1.f / 256.f);
    float v = 0.f;
#pragma unroll
    for (int j = 0; j < 8; j++) {
        const float t = x[j] - mu;
        v += t * t;
    }
    v = wredsum(v);
    const float r = rsqrtf(v * (1.f / 256.f) + 1e-5f);
#pragma unroll
    for (int j = 0; j < 8; j++) {
        const int dim = lane + 32 * j;
        g_hn[(size_t)w * 256 + dim] = (x[j] - mu) * r * gam[dim] + bet[dim];
    }
}

// ---------------- launch ----------------
extern "C" void kernel_launch(void* const* d_in, const int* in_sizes, int n_in,
                              void* d_out, int out_size) {
    const int*   atom_types = (const int*)d_in[0];
    const float* lattices   = (const float*)d_in[1];
    const float* frac       = (const float*)d_in[2];
    const int*   eidx       = (const int*)d_in[3];
    const float* shifts     = (const float*)d_in[4];
    const int*   bids       = (const int*)d_in[5];
    const float* atom_emb   = (const float*)d_in[6];
    const float* node_W     = (const float*)d_in[7];
    const float* node_b     = (const float*)d_in[8];
    const float* edge_W     = (const float*)d_in[9];
    const float* edge_b     = (const float*)d_in[10];
    const float* Wq         = (const float*)d_in[11];
    const float* bq         = (const float*)d_in[12];
    const float* Wkv        = (const float*)d_in[13];
    const float* bkv        = (const float*)d_in[14];
    const float* Wo         = (const float*)d_in[15];
    const float* bo         = (const float*)d_in[16];
    const float* ln1_g      = (const float*)d_in[17];
    const float* ln1_b      = (const float*)d_in[18];
    const float* W1         = (const float*)d_in[19];
    const float* b1         = (const float*)d_in[20];
    const float* W2         = (const float*)d_in[21];
    const float* b2         = (const float*)d_in[22];
    const float* ln2_g      = (const float*)d_in[23];
    const float* ln2_b      = (const float*)d_in[24];
    const int* src = eidx;
    const int* dst = eidx + EE;

    float *pXnode, *pXedge, *phn, *pQKVn, *pattn, *pffn1, *ptmp;
    float *pWn, *pWe, *pWvBD, *pbqkv;
    __half *pheH, *pQKeH, *paggGH;
    int *pdeg, *prow, *ppos;
    cudaGetSymbolAddress((void**)&pXnode, g_Xnode);
    cudaGetSymbolAddress((void**)&pXedge, g_Xedge);
    cudaGetSymbolAddress((void**)&phn, g_hn);
    cudaGetSymbolAddress((void**)&pheH, g_heH);
    cudaGetSymbolAddress((void**)&pQKVn, g_QKVn);
    cudaGetSymbolAddress((void**)&pQKeH, g_QKeH);
    cudaGetSymbolAddress((void**)&pattn, g_attn);
    cudaGetSymbolAddress((void**)&paggGH, g_aggGH);
    cudaGetSymbolAddress((void**)&pffn1, g_ffn1);
    cudaGetSymbolAddress((void**)&ptmp, g_tmp);
    cudaGetSymbolAddress((void**)&pWn, g_Wn);
    cudaGetSymbolAddress((void**)&pWe, g_We);
    cudaGetSymbolAddress((void**)&pWvBD, g_WvBD);
    cudaGetSymbolAddress((void**)&pbqkv, g_bqkv);
    cudaGetSymbolAddress((void**)&pdeg, g_deg);
    cudaGetSymbolAddress((void**)&prow, g_rowptr);
    cudaGetSymbolAddress((void**)&ppos, g_pos);

    const int MB_N = (NN + 127) / 128;   // 63
    const int MB_E = (EE + 127) / 128;   // 1563
    const float* nul = (const float*)0;

    // ---- weight packing ----
    k_pack<<<(LLAYERS * 256 * 768 + 255) / 256, 256>>>(Wq, Wkv);
    k_packe<<<(LLAYERS * 256 * 512 + 255) / 256, 256>>>(Wq, Wkv);
    k_packvbd<<<(LLAYERS * 1024 * 256 + 255) / 256, 256>>>(Wkv);
    k_packb<<<(LLAYERS * 768 + 255) / 256, 256>>>(bq, bkv);

    // ---- front end ----
    k_lfeat<<<1, 96>>>(lattices);
    k_xnode<<<(NN * KPAD_NODE + 255) / 256, 256>>>(atom_types, bids, atom_emb);
    tgemm_k<0, 0, 0><<<dim3(2, MB_N), 256>>>(NN, 262, pXnode, KPAD_NODE, node_W, 256, node_b, nul, phn, 256);
    k_edgefeat<<<(EE + 15) / 16, 128>>>(frac, shifts, src, dst);
    tgemm_k<0, 0, 1><<<dim3(2, MB_E), 256>>>(EE, 600, pXedge, KPAD_EDGE, edge_W, 256, edge_b, nul, pheH, 256);

    // ---- CSR (src-grouped) ----
    cudaMemsetAsync(pdeg, 0, NN * sizeof(int));
    k_hist<<<(EE + 255) / 256, 256>>>(src);
    k_scan<<<1, 1024>>>();
    cudaMemcpyAsync(ppos, prow, NN * sizeof(int), cudaMemcpyDeviceToDevice);
    k_scatter<<<(EE + 255) / 256, 256>>>(src);

    // ---- fused 4-layer edge Q|K projection: E x 256 @ 256 x 2048 (A fp16, C fp16) ----
    tgemm_k<0, 1, 1><<<dim3(16, MB_E), 256>>>(EE, 256, pheH, 256, pWe, 2048, nul, nul, pQKeH, 2048);

    // ---- transformer layers ----
    for (int i = 0; i < LLAYERS; i++) {
        const float* wn = pWn + (size_t)i * 256 * 768;
        const int loff = i * 512;
        // node QKV projection (depends on current h_n)
        tgemm_k<0, 0, 0><<<dim3(6, MB_N), 256>>>(NN, 256, phn, 256, wn, 768, pbqkv + i * 768, nul, pQKVn, 768);
        // attention
        k_scores<<<(EE + 7) / 8, 256>>>(src, dst, loff);
        k_softmax<<<(NN + 7) / 8, 256>>>();
        k_agg<<<(NN + 7) / 8, 256>>>(dst);
        // attn = A + G @ WvBD  (in place on g_attn; A fp16 input)
        tgemm_k<0, 1, 0><<<dim3(2, MB_N), 256>>>(NN, 1024, paggGH, 1024, pWvBD + (size_t)i * 1024 * 256, 256, nul, pattn, pattn, 256);
        tgemm_k<0, 0, 0><<<dim3(2, MB_N), 256>>>(NN, 256, pattn, 256, Wo + (size_t)i * 256 * 256, 256, bo + i * 256, nul, ptmp, 256);
        k_resln<<<(NN + 7) / 8, 256>>>(ptmp, ln1_g + i * 256, ln1_b + i * 256);
        // FFN
        tgemm_k<1, 0, 0><<<dim3(8, MB_N), 256>>>(NN, 256, phn, 256, W1 + (size_t)i * 256 * 1024, 1024, b1 + i * 1024, nul, pffn1, 1024);
        tgemm_k<0, 0, 0><<<dim3(2, MB_N), 256>>>(NN, 1024, pffn1, 1024, W2 + (size_t)i * 1024 * 256, 256, b2 + i * 256, nul, ptmp, 256);
        k_resln<<<(NN + 7) / 8, 256>>>(ptmp, ln2_g + i * 256, ln2_b + i * 256);
    }

    cudaMemcpyAsync(d_out, phn, (size_t)NN * 256 * sizeof(float), cudaMemcpyDeviceToDevice);
}